// round 1
// baseline (speedup 1.0000x reference)
#include <cuda_runtime.h>
#include <cstdint>

#define F_DIM 300
#define DIN_MAX 303
#define MAX_NLAST 100000
#define MAX_NCUR  50000
#define MAX_E     500000

// ---------------- scratch (static __device__ globals; no allocation) ----------------
__device__ float d_PC[(size_t)MAX_NLAST * F_DIM];     // [N_last,300] = feat@W1a + coor@W1b + b1
__device__ float d_c2[(size_t)MAX_NCUR * F_DIM];      // [N_cur,300]  = ccoor@W1b
__device__ float d_aggmax[(size_t)MAX_NCUR * F_DIM];  // per-segment max of relu(z); -1 sentinel = empty
__device__ float d_aggmin[(size_t)MAX_NCUR * F_DIM];
__device__ float d_agg[(size_t)MAX_NCUR * F_DIM];     // BN1 applied
__device__ float d_ypre[(size_t)MAX_NCUR * F_DIM];    // relu(agg@W2+b2)
__device__ int   d_counts[MAX_NCUR];
__device__ int   d_offsets[MAX_NCUR];
__device__ int   d_cursor[MAX_NCUR];
__device__ int   d_edge_order[MAX_E];
__device__ float d_colsum1[F_DIM], d_colsq1[F_DIM];
__device__ float d_colsum2[F_DIM], d_colsq2[F_DIM];
__device__ float d_scale1[F_DIM], d_shift1[F_DIM];
__device__ float d_scale2[F_DIM], d_shift2[F_DIM];

// ---------------- kernels ----------------

__global__ void reset_kernel(int ncur) {
    int i = blockIdx.x * blockDim.x + threadIdx.x;
    if (i < ncur) d_counts[i] = 0;
    if (i < F_DIM) {
        d_colsum1[i] = 0.f; d_colsq1[i] = 0.f;
        d_colsum2[i] = 0.f; d_colsq2[i] = 0.f;
    }
}

// C[M,300] = A[M,K] @ W[K,300] + bias  (optionally relu + per-column sum/sumsq)
// A element (row,k): k<300 -> Afeat[row*300+k], else Acoor[row*3+(k-300)]  (concat layout)
// BM=64, BN=64, BK=16, 128 threads, per-thread micro-tile 4x8.
__global__ __launch_bounds__(128) void gemm_kernel(
    const float* __restrict__ Afeat, const float* __restrict__ Acoor,
    int M, int K,
    const float* __restrict__ W, const float* __restrict__ bias,
    float* __restrict__ C,
    int doRelu, float* __restrict__ colsum, float* __restrict__ colsq)
{
    __shared__ float As[16][64];
    __shared__ float Ws[16][64];
    __shared__ float red[16][64];

    const int tid = threadIdx.x;      // 0..127
    const int tr  = tid >> 3;         // 0..15 (row group: 4 rows)
    const int tc  = tid & 7;          // 0..7  (col group: 8 cols)
    const int m0  = blockIdx.y * 64;
    const int c0  = blockIdx.x * 64;

    float acc[4][8];
#pragma unroll
    for (int r = 0; r < 4; r++)
#pragma unroll
        for (int j = 0; j < 8; j++) acc[r][j] = 0.f;

    const int lrow = tid >> 1;        // A load: row within tile 0..63
    const int lk0  = (tid & 1) * 8;   // 0 or 8
    const int wkr  = tid >> 3;        // W load: k-row 0..15
    const int wc0  = (tid & 7) * 8;   // W load: col base

    for (int k0 = 0; k0 < K; k0 += 16) {
        // load A tile (transposed into smem)
        {
            int gm = m0 + lrow;
#pragma unroll
            for (int i = 0; i < 8; i++) {
                int k = k0 + lk0 + i;
                float v = 0.f;
                if (gm < M && k < K)
                    v = (k < F_DIM) ? Afeat[(size_t)gm * F_DIM + k]
                                    : Acoor[(size_t)gm * 3 + (k - F_DIM)];
                As[lk0 + i][lrow] = v;
            }
        }
        // load W tile
        {
            int k = k0 + wkr;
#pragma unroll
            for (int i = 0; i < 8; i++) {
                int c = c0 + wc0 + i;
                Ws[wkr][wc0 + i] = (k < K && c < F_DIM) ? W[(size_t)k * F_DIM + c] : 0.f;
            }
        }
        __syncthreads();
#pragma unroll
        for (int kk = 0; kk < 16; kk++) {
            float a[4], w[8];
#pragma unroll
            for (int r = 0; r < 4; r++) a[r] = As[kk][tr * 4 + r];
#pragma unroll
            for (int j = 0; j < 8; j++) w[j] = Ws[kk][tc * 8 + j];
#pragma unroll
            for (int r = 0; r < 4; r++)
#pragma unroll
                for (int j = 0; j < 8; j++)
                    acc[r][j] = fmaf(a[r], w[j], acc[r][j]);
        }
        __syncthreads();
    }

    // epilogue: bias (+relu), store, per-column stats
    float cs[8], cq[8];
#pragma unroll
    for (int j = 0; j < 8; j++) {
        int col = c0 + tc * 8 + j;
        float s = 0.f, q = 0.f;
        if (col < F_DIM) {
            float b = bias[col];
#pragma unroll
            for (int r = 0; r < 4; r++) {
                int row = m0 + tr * 4 + r;
                if (row < M) {
                    float v = acc[r][j] + b;
                    if (doRelu) v = fmaxf(v, 0.f);
                    C[(size_t)row * F_DIM + col] = v;
                    s += v; q += v * v;
                }
            }
        }
        cs[j] = s; cq[j] = q;
    }

    if (colsum) {
#pragma unroll
        for (int j = 0; j < 8; j++) red[tr][tc * 8 + j] = cs[j];
        __syncthreads();
        if (tid < 64) {
            float t = 0.f;
#pragma unroll
            for (int r = 0; r < 16; r++) t += red[r][tid];
            int col = c0 + tid;
            if (col < F_DIM) atomicAdd(&colsum[col], t);
        }
        __syncthreads();
#pragma unroll
        for (int j = 0; j < 8; j++) red[tr][tc * 8 + j] = cq[j];
        __syncthreads();
        if (tid < 64) {
            float t = 0.f;
#pragma unroll
            for (int r = 0; r < 16; r++) t += red[r][tid];
            int col = c0 + tid;
            if (col < F_DIM) atomicAdd(&colsq[col], t);
        }
    }
}

// c2[i,c] = ccoor[i]·W1[300..302, c]
__global__ void c2_kernel(const float* __restrict__ ccoors, const float* __restrict__ W1, int ncur) {
    int idx = blockIdx.x * blockDim.x + threadIdx.x;
    if (idx >= ncur * F_DIM) return;
    int i = idx / F_DIM, c = idx % F_DIM;
    float x = ccoors[3 * i], y = ccoors[3 * i + 1], z = ccoors[3 * i + 2];
    d_c2[idx] = x * W1[(size_t)300 * F_DIM + c]
              + y * W1[(size_t)301 * F_DIM + c]
              + z * W1[(size_t)302 * F_DIM + c];
}

__global__ void count_kernel(const int* __restrict__ cur_idx, int E) {
    int e = blockIdx.x * blockDim.x + threadIdx.x;
    if (e < E) atomicAdd(&d_counts[cur_idx[e]], 1);
}

// single-block exclusive scan of d_counts -> d_offsets, d_cursor
__global__ void scan_kernel(int n) {
    __shared__ int buf[1024];
    __shared__ int carry_s;
    int tid = threadIdx.x;
    if (tid == 0) carry_s = 0;
    __syncthreads();
    for (int base = 0; base < n; base += 1024) {
        int i = base + tid;
        int x = (i < n) ? d_counts[i] : 0;
        buf[tid] = x;
        __syncthreads();
        for (int off = 1; off < 1024; off <<= 1) {
            int v = (tid >= off) ? buf[tid - off] : 0;
            __syncthreads();
            buf[tid] += v;
            __syncthreads();
        }
        int carry = carry_s;
        int excl = carry + buf[tid] - x;
        if (i < n) { d_offsets[i] = excl; d_cursor[i] = excl; }
        __syncthreads();
        if (tid == 1023) carry_s = carry + buf[1023];
        __syncthreads();
    }
}

__global__ void scatter_kernel(const int* __restrict__ cur_idx, int E) {
    int e = blockIdx.x * blockDim.x + threadIdx.x;
    if (e < E) {
        int p = atomicAdd(&d_cursor[cur_idx[e]], 1);
        d_edge_order[p] = e;
    }
}

// per-segment: running max/min of relu(PC[l]-c2[i]) over edges + global BN1 stats
#define SEGS_PER_BLOCK 8
__global__ __launch_bounds__(128) void seg_kernel(const int* __restrict__ last_idx, int ncur) {
    const int tid = threadIdx.x;  // 128
    float s[3] = {0.f, 0.f, 0.f}, q[3] = {0.f, 0.f, 0.f};
    int segBeg = blockIdx.x * SEGS_PER_BLOCK;
    int segEnd = min(segBeg + SEGS_PER_BLOCK, ncur);
    for (int seg = segBeg; seg < segEnd; seg++) {
        float c2v[3], mx[3], mn[3];
#pragma unroll
        for (int j = 0; j < 3; j++) {
            int c = tid + j * 128;
            c2v[j] = (c < F_DIM) ? d_c2[(size_t)seg * F_DIM + c] : 0.f;
            mx[j] = -1.f;
            mn[j] = 3.4e38f;
        }
        int off = d_offsets[seg];
        int cnt = d_counts[seg];
        for (int t = 0; t < cnt; t++) {
            int e = d_edge_order[off + t];
            int l = __ldg(&last_idx[e]);
            const float* pr = d_PC + (size_t)l * F_DIM;
#pragma unroll
            for (int j = 0; j < 3; j++) {
                int c = tid + j * 128;
                if (c < F_DIM) {
                    float v = fmaxf(pr[c] - c2v[j], 0.f);
                    s[j] += v; q[j] += v * v;
                    mx[j] = fmaxf(mx[j], v);
                    mn[j] = fminf(mn[j], v);
                }
            }
        }
#pragma unroll
        for (int j = 0; j < 3; j++) {
            int c = tid + j * 128;
            if (c < F_DIM) {
                d_aggmax[(size_t)seg * F_DIM + c] = mx[j];            // -1 == empty segment
                d_aggmin[(size_t)seg * F_DIM + c] = (cnt > 0) ? mn[j] : 0.f;
            }
        }
    }
#pragma unroll
    for (int j = 0; j < 3; j++) {
        int c = tid + j * 128;
        if (c < F_DIM) {
            atomicAdd(&d_colsum1[c], s[j]);
            atomicAdd(&d_colsq1[c], q[j]);
        }
    }
}

__global__ void bnparam_kernel(const float* __restrict__ colsum, const float* __restrict__ colsq,
                               float invN, const float* __restrict__ g, const float* __restrict__ be,
                               float* __restrict__ scale, float* __restrict__ shift) {
    int c = blockIdx.x * blockDim.x + threadIdx.x;
    if (c >= F_DIM) return;
    float mean = colsum[c] * invN;
    float var = colsq[c] * invN - mean * mean;
    if (var < 0.f) var = 0.f;
    float sc = g[c] * rsqrtf(var + 1e-5f);
    scale[c] = sc;
    shift[c] = be[c] - mean * sc;
}

// agg = BN1 applied to per-segment max (or min if scale<0); empty -> 0
__global__ void apply_agg_kernel(int ncur) {
    int idx = blockIdx.x * blockDim.x + threadIdx.x;
    if (idx >= ncur * F_DIM) return;
    int c = idx % F_DIM;
    float m = d_aggmax[idx];
    float v = 0.f;
    if (m >= 0.f) {
        float sc = d_scale1[c];
        float base = (sc >= 0.f) ? m : d_aggmin[idx];
        v = fmaf(base, sc, d_shift1[c]);
    }
    d_agg[idx] = v;
}

__global__ void apply_out_kernel(float* __restrict__ out, int ncur) {
    int idx = blockIdx.x * blockDim.x + threadIdx.x;
    if (idx >= ncur * F_DIM) return;
    int c = idx % F_DIM;
    out[idx] = fmaf(d_ypre[idx], d_scale2[c], d_shift2[c]);
}

// ---------------- launcher ----------------
extern "C" void kernel_launch(void* const* d_in, const int* in_sizes, int n_in,
                              void* d_out, int out_size) {
    const float* last_coors    = (const float*)d_in[0];
    const float* last_features = (const float*)d_in[1];
    const float* current_coors = (const float*)d_in[2];
    const int*   cur_idx       = (const int*)d_in[3];
    const int*   last_idx      = (const int*)d_in[4];
    const float* W1            = (const float*)d_in[5];
    const float* b1            = (const float*)d_in[6];
    const float* g1            = (const float*)d_in[7];
    const float* be1           = (const float*)d_in[8];
    const float* W2            = (const float*)d_in[9];
    const float* b2            = (const float*)d_in[10];
    const float* g2            = (const float*)d_in[11];
    const float* be2           = (const float*)d_in[12];

    const int Nlast = in_sizes[0] / 3;
    const int Ncur  = in_sizes[2] / 3;
    const int E     = in_sizes[3];
    const int Din   = in_sizes[5] / F_DIM;  // 303

    // symbol addresses (not allocations; capture-safe host-side queries)
    float *pPC, *pAgg, *pYpre, *pSum1, *pSq1, *pSum2, *pSq2, *pSc1, *pSh1, *pSc2, *pSh2;
    cudaGetSymbolAddress((void**)&pPC,   d_PC);
    cudaGetSymbolAddress((void**)&pAgg,  d_agg);
    cudaGetSymbolAddress((void**)&pYpre, d_ypre);
    cudaGetSymbolAddress((void**)&pSum1, d_colsum1);
    cudaGetSymbolAddress((void**)&pSq1,  d_colsq1);
    cudaGetSymbolAddress((void**)&pSum2, d_colsum2);
    cudaGetSymbolAddress((void**)&pSq2,  d_colsq2);
    cudaGetSymbolAddress((void**)&pSc1,  d_scale1);
    cudaGetSymbolAddress((void**)&pSh1,  d_shift1);
    cudaGetSymbolAddress((void**)&pSc2,  d_scale2);
    cudaGetSymbolAddress((void**)&pSh2,  d_shift2);

    const int NT = (F_DIM + 63) / 64;  // 5 col tiles

    reset_kernel<<<(Ncur + 255) / 256, 256>>>(Ncur);

    // PC = [feat, coor] @ W1 + b1   (no relu, no stats)
    gemm_kernel<<<dim3(NT, (Nlast + 63) / 64), 128>>>(
        last_features, last_coors, Nlast, Din, W1, b1, pPC, 0, nullptr, nullptr);

    c2_kernel<<<(Ncur * F_DIM + 255) / 256, 256>>>(current_coors, W1, Ncur);

    count_kernel<<<(E + 255) / 256, 256>>>(cur_idx, E);
    scan_kernel<<<1, 1024>>>(Ncur);
    scatter_kernel<<<(E + 255) / 256, 256>>>(cur_idx, E);

    seg_kernel<<<(Ncur + SEGS_PER_BLOCK - 1) / SEGS_PER_BLOCK, 128>>>(last_idx, Ncur);

    bnparam_kernel<<<(F_DIM + 127) / 128, 128>>>(pSum1, pSq1, 1.0f / (float)E, g1, be1, pSc1, pSh1);
    apply_agg_kernel<<<(Ncur * F_DIM + 255) / 256, 256>>>(Ncur);

    // ypre = relu(agg @ W2 + b2), with BN2 stats
    gemm_kernel<<<dim3(NT, (Ncur + 63) / 64), 128>>>(
        pAgg, nullptr, Ncur, F_DIM, W2, b2, pYpre, 1, pSum2, pSq2);

    bnparam_kernel<<<(F_DIM + 127) / 128, 128>>>(pSum2, pSq2, 1.0f / (float)Ncur, g2, be2, pSc2, pSh2);
    apply_out_kernel<<<(Ncur * F_DIM + 255) / 256, 256>>>((float*)d_out, Ncur);
}

// round 2
// speedup vs baseline: 1.6120x; 1.6120x over previous
#include <cuda_runtime.h>
#include <cstdint>

#define F_DIM 300
#define MAX_NLAST 100000
#define MAX_NCUR  50000
#define MAX_E     500000

typedef unsigned long long u64;

__device__ __forceinline__ u64 pack2(float lo, float hi) {
    u64 r; asm("mov.b64 %0,{%1,%2};" : "=l"(r) : "f"(lo), "f"(hi)); return r;
}
__device__ __forceinline__ u64 fma2(u64 a, u64 b, u64 c) {
    u64 d; asm("fma.rn.f32x2 %0,%1,%2,%3;" : "=l"(d) : "l"(a), "l"(b), "l"(c)); return d;
}
__device__ __forceinline__ float2 unpack2(u64 v) {
    float2 f; asm("mov.b64 {%0,%1},%2;" : "=f"(f.x), "=f"(f.y) : "l"(v)); return f;
}

// ---------------- scratch ----------------
__device__ float d_PC[(size_t)MAX_NLAST * F_DIM];
__device__ float d_c2[(size_t)MAX_NCUR * F_DIM];
__device__ float d_aggmax[(size_t)MAX_NCUR * F_DIM];
__device__ float d_aggmin[(size_t)MAX_NCUR * F_DIM];
__device__ float d_agg[(size_t)MAX_NCUR * F_DIM];
__device__ float d_ypre[(size_t)MAX_NCUR * F_DIM];
__device__ int   d_counts[MAX_NCUR];
__device__ int   d_offsets[MAX_NCUR];
__device__ int   d_cursor[MAX_NCUR];
__device__ int   d_edge_l[MAX_E];      // gathered last_idx value per CSR slot
__device__ float d_colsum1[F_DIM], d_colsq1[F_DIM];
__device__ float d_colsum2[F_DIM], d_colsq2[F_DIM];
__device__ float d_scale1[F_DIM], d_shift1[F_DIM];
__device__ float d_scale2[F_DIM], d_shift2[F_DIM];

// ---------------- small kernels ----------------
__global__ void reset_kernel(int ncur) {
    int i = blockIdx.x * blockDim.x + threadIdx.x;
    if (i < ncur) d_counts[i] = 0;
    if (i < F_DIM) {
        d_colsum1[i] = 0.f; d_colsq1[i] = 0.f;
        d_colsum2[i] = 0.f; d_colsq2[i] = 0.f;
    }
}

__global__ void c2_kernel(const float* __restrict__ ccoors, const float* __restrict__ W1, int ncur) {
    int idx = blockIdx.x * blockDim.x + threadIdx.x;
    if (idx >= ncur * F_DIM) return;
    int i = idx / F_DIM, c = idx % F_DIM;
    float x = ccoors[3 * i], y = ccoors[3 * i + 1], z = ccoors[3 * i + 2];
    d_c2[idx] = x * W1[(size_t)300 * F_DIM + c]
              + y * W1[(size_t)301 * F_DIM + c]
              + z * W1[(size_t)302 * F_DIM + c];
}

__global__ void count_kernel(const int* __restrict__ cur_idx, int E) {
    int e = blockIdx.x * blockDim.x + threadIdx.x;
    if (e < E) atomicAdd(&d_counts[cur_idx[e]], 1);
}

__global__ void scan_kernel(int n) {
    __shared__ int buf[1024];
    __shared__ int carry_s;
    int tid = threadIdx.x;
    if (tid == 0) carry_s = 0;
    __syncthreads();
    for (int base = 0; base < n; base += 1024) {
        int i = base + tid;
        int x = (i < n) ? d_counts[i] : 0;
        buf[tid] = x;
        __syncthreads();
        for (int off = 1; off < 1024; off <<= 1) {
            int v = (tid >= off) ? buf[tid - off] : 0;
            __syncthreads();
            buf[tid] += v;
            __syncthreads();
        }
        int carry = carry_s;
        int excl = carry + buf[tid] - x;
        if (i < n) { d_offsets[i] = excl; d_cursor[i] = excl; }
        __syncthreads();
        if (tid == 1023) carry_s = carry + buf[1023];
        __syncthreads();
    }
}

__global__ void scatter_kernel(const int* __restrict__ cur_idx, const int* __restrict__ last_idx, int E) {
    int e = blockIdx.x * blockDim.x + threadIdx.x;
    if (e < E) {
        int p = atomicAdd(&d_cursor[cur_idx[e]], 1);
        d_edge_l[p] = last_idx[e];   // store gathered row index directly
    }
}

// ---------------- GEMM: C[M,300] = A[M,K]@W[K,300]+bias (opt relu+stats) ----------------
// BM=128, BN=64, BK=16, 128 threads, microtile 8x8 via f32x2 packed FMA.
// A concat layout: k<300 -> Afeat[row*300+k], else Acoor[row*3+(k-300)].
#define BM 128
#define BN 64
#define BK 16

__global__ __launch_bounds__(128) void gemm_kernel(
    const float* __restrict__ Afeat, const float* __restrict__ Acoor,
    int M, int K,
    const float* __restrict__ W, const float* __restrict__ bias,
    float* __restrict__ C,
    int doRelu, float* __restrict__ colsum, float* __restrict__ colsq)
{
    __shared__ float As[BK][BM];   // transposed A tile, 8KB
    __shared__ float Ws[BK][BN];   // 4KB

    const int tid = threadIdx.x;      // 0..127
    const int tr  = tid >> 3;         // 0..15 -> rows tr*8..tr*8+7
    const int tc  = tid & 7;          // 0..7  -> cols tc*8..tc*8+7
    const int m0  = blockIdx.y * BM;
    const int c0  = blockIdx.x * BN;

    u64 acc[4][8];                    // [row-pair][col] packed (row 2rp, 2rp+1)
#pragma unroll
    for (int rp = 0; rp < 4; rp++)
#pragma unroll
        for (int c = 0; c < 8; c++) acc[rp][c] = 0ull;

    const int wk = tid >> 3;          // W load: k row 0..15
    const int wc = (tid & 7) * 8;     // W load: col base

    for (int k0 = 0; k0 < K; k0 += BK) {
        // ---- load A tile (one row per thread, 16 k) into transposed smem ----
        {
            int gm = m0 + tid;
            if (gm < M && k0 + BK <= F_DIM && k0 + BK <= K) {
                const float* ap = Afeat + (size_t)gm * F_DIM + k0;
#pragma unroll
                for (int i = 0; i < 4; i++) {
                    float4 v = *(const float4*)(ap + 4 * i);
                    As[4 * i + 0][tid] = v.x;
                    As[4 * i + 1][tid] = v.y;
                    As[4 * i + 2][tid] = v.z;
                    As[4 * i + 3][tid] = v.w;
                }
            } else {
#pragma unroll
                for (int i = 0; i < BK; i++) {
                    int k = k0 + i; float v = 0.f;
                    if (gm < M && k < K)
                        v = (k < F_DIM) ? Afeat[(size_t)gm * F_DIM + k]
                                        : Acoor[(size_t)gm * 3 + (k - F_DIM)];
                    As[i][tid] = v;
                }
            }
        }
        // ---- load W tile ----
        {
            int k = k0 + wk;
            if (k < K && c0 + wc + 8 <= F_DIM) {
                const float4* wp = (const float4*)(W + (size_t)k * F_DIM + c0 + wc);
                *(float4*)&Ws[wk][wc]     = wp[0];
                *(float4*)&Ws[wk][wc + 4] = wp[1];
            } else {
#pragma unroll
                for (int i = 0; i < 8; i++) {
                    int c = c0 + wc + i;
                    Ws[wk][wc + i] = (k < K && c < F_DIM) ? W[(size_t)k * F_DIM + c] : 0.f;
                }
            }
        }
        __syncthreads();

#pragma unroll
        for (int kk = 0; kk < BK; kk++) {
            u64 a2[4];
            const u64* ap2 = (const u64*)&As[kk][tr * 8];
            a2[0] = ap2[0]; a2[1] = ap2[1]; a2[2] = ap2[2]; a2[3] = ap2[3];
            float wv[8];
            *(float4*)&wv[0] = *(const float4*)&Ws[kk][tc * 8];
            *(float4*)&wv[4] = *(const float4*)&Ws[kk][tc * 8 + 4];
#pragma unroll
            for (int c = 0; c < 8; c++) {
                u64 w2 = pack2(wv[c], wv[c]);
#pragma unroll
                for (int rp = 0; rp < 4; rp++)
                    acc[rp][c] = fma2(a2[rp], w2, acc[rp][c]);
            }
        }
        __syncthreads();
    }

    // ---- epilogue: bias (+relu), store, per-column stats ----
    float cs[8], cq[8], bv[8];
#pragma unroll
    for (int c = 0; c < 8; c++) {
        int col = c0 + tc * 8 + c;
        bv[c] = (col < F_DIM) ? bias[col] : 0.f;
        cs[c] = 0.f; cq[c] = 0.f;
    }
#pragma unroll
    for (int rp = 0; rp < 4; rp++) {
        int row0 = m0 + tr * 8 + rp * 2;
#pragma unroll
        for (int half = 0; half < 2; half++) {
            int row = row0 + half;
            if (row < M) {
#pragma unroll
                for (int c = 0; c < 8; c++) {
                    float2 f = unpack2(acc[rp][c]);
                    float v = (half ? f.y : f.x) + bv[c];
                    if (doRelu) v = fmaxf(v, 0.f);
                    int col = c0 + tc * 8 + c;
                    if (col < F_DIM) {
                        C[(size_t)row * F_DIM + col] = v;
                        cs[c] += v; cq[c] += v * v;
                    }
                }
            }
        }
    }

    if (colsum) {
        float (*red)[BN] = (float(*)[BN])As;   // reuse As (8KB >= 4KB)
        __syncthreads();
#pragma unroll
        for (int c = 0; c < 8; c++) red[tr][tc * 8 + c] = cs[c];
        __syncthreads();
        if (tid < BN) {
            float t = 0.f;
#pragma unroll
            for (int r = 0; r < 16; r++) t += red[r][tid];
            int col = c0 + tid;
            if (col < F_DIM) atomicAdd(&colsum[col], t);
        }
        __syncthreads();
#pragma unroll
        for (int c = 0; c < 8; c++) red[tr][tc * 8 + c] = cq[c];
        __syncthreads();
        if (tid < BN) {
            float t = 0.f;
#pragma unroll
            for (int r = 0; r < 16; r++) t += red[r][tid];
            int col = c0 + tid;
            if (col < F_DIM) atomicAdd(&colsq[col], t);
        }
    }
}

// ---------------- segment max/min + BN1 stats ----------------
#define SEGS_PER_BLOCK 4
__global__ __launch_bounds__(128) void seg_kernel(int ncur) {
    const int tid = threadIdx.x;          // 128
    const int ca = tid, cb = tid + 128, cc = tid + 256;
    const bool h2 = (cc < F_DIM);         // tid < 44
    float s0 = 0.f, s1 = 0.f, s2 = 0.f, q0 = 0.f, q1 = 0.f, q2 = 0.f;

    int segBeg = blockIdx.x * SEGS_PER_BLOCK;
    int segEnd = min(segBeg + SEGS_PER_BLOCK, ncur);
    for (int seg = segBeg; seg < segEnd; seg++) {
        const float* c2r = d_c2 + (size_t)seg * F_DIM;
        float cA = c2r[ca], cB = c2r[cb], cC = h2 ? c2r[cc] : 0.f;
        float mxA = -1.f, mxB = -1.f, mxC = -1.f;
        float mnA = 3.4e38f, mnB = 3.4e38f, mnC = 3.4e38f;
        int off = d_offsets[seg], cnt = d_counts[seg];
        int t = 0;
        for (; t + 4 <= cnt; t += 4) {
            int l[4];
#pragma unroll
            for (int u = 0; u < 4; u++) l[u] = d_edge_l[off + t + u];
            float vA[4], vB[4], vC[4];
#pragma unroll
            for (int u = 0; u < 4; u++) {
                const float* p = d_PC + (size_t)l[u] * F_DIM;
                vA[u] = p[ca]; vB[u] = p[cb]; vC[u] = h2 ? p[cc] : 0.f;
            }
#pragma unroll
            for (int u = 0; u < 4; u++) {
                float a = fmaxf(vA[u] - cA, 0.f);
                float b = fmaxf(vB[u] - cB, 0.f);
                float c = fmaxf(vC[u] - cC, 0.f);
                s0 += a; q0 += a * a; mxA = fmaxf(mxA, a); mnA = fminf(mnA, a);
                s1 += b; q1 += b * b; mxB = fmaxf(mxB, b); mnB = fminf(mnB, b);
                s2 += c; q2 += c * c; mxC = fmaxf(mxC, c); mnC = fminf(mnC, c);
            }
        }
        for (; t < cnt; t++) {
            int lv = d_edge_l[off + t];
            const float* p = d_PC + (size_t)lv * F_DIM;
            float a = fmaxf(p[ca] - cA, 0.f);
            float b = fmaxf(p[cb] - cB, 0.f);
            float c = h2 ? fmaxf(p[cc] - cC, 0.f) : 0.f;
            s0 += a; q0 += a * a; mxA = fmaxf(mxA, a); mnA = fminf(mnA, a);
            s1 += b; q1 += b * b; mxB = fmaxf(mxB, b); mnB = fminf(mnB, b);
            s2 += c; q2 += c * c; mxC = fmaxf(mxC, c); mnC = fminf(mnC, c);
        }
        size_t base = (size_t)seg * F_DIM;
        d_aggmax[base + ca] = mxA; d_aggmin[base + ca] = cnt ? mnA : 0.f;
        d_aggmax[base + cb] = mxB; d_aggmin[base + cb] = cnt ? mnB : 0.f;
        if (h2) { d_aggmax[base + cc] = mxC; d_aggmin[base + cc] = cnt ? mnC : 0.f; }
    }
    atomicAdd(&d_colsum1[ca], s0); atomicAdd(&d_colsq1[ca], q0);
    atomicAdd(&d_colsum1[cb], s1); atomicAdd(&d_colsq1[cb], q1);
    if (h2) { atomicAdd(&d_colsum1[cc], s2); atomicAdd(&d_colsq1[cc], q2); }
}

__global__ void bnparam_kernel(const float* __restrict__ colsum, const float* __restrict__ colsq,
                               float invN, const float* __restrict__ g, const float* __restrict__ be,
                               float* __restrict__ scale, float* __restrict__ shift) {
    int c = blockIdx.x * blockDim.x + threadIdx.x;
    if (c >= F_DIM) return;
    float mean = colsum[c] * invN;
    float var = colsq[c] * invN - mean * mean;
    if (var < 0.f) var = 0.f;
    float sc = g[c] * rsqrtf(var + 1e-5f);
    scale[c] = sc;
    shift[c] = be[c] - mean * sc;
}

__global__ void apply_agg_kernel(int ncur) {
    int idx = blockIdx.x * blockDim.x + threadIdx.x;
    if (idx >= ncur * F_DIM) return;
    int c = idx % F_DIM;
    float m = d_aggmax[idx];
    float v = 0.f;
    if (m >= 0.f) {
        float sc = d_scale1[c];
        float base = (sc >= 0.f) ? m : d_aggmin[idx];
        v = fmaf(base, sc, d_shift1[c]);
    }
    d_agg[idx] = v;
}

__global__ void apply_out_kernel(float* __restrict__ out, int ncur) {
    int idx = blockIdx.x * blockDim.x + threadIdx.x;
    if (idx >= ncur * F_DIM) return;
    int c = idx % F_DIM;
    out[idx] = fmaf(d_ypre[idx], d_scale2[c], d_shift2[c]);
}

// ---------------- launcher ----------------
extern "C" void kernel_launch(void* const* d_in, const int* in_sizes, int n_in,
                              void* d_out, int out_size) {
    const float* last_coors    = (const float*)d_in[0];
    const float* last_features = (const float*)d_in[1];
    const float* current_coors = (const float*)d_in[2];
    const int*   cur_idx       = (const int*)d_in[3];
    const int*   last_idx      = (const int*)d_in[4];
    const float* W1            = (const float*)d_in[5];
    const float* b1            = (const float*)d_in[6];
    const float* g1            = (const float*)d_in[7];
    const float* be1           = (const float*)d_in[8];
    const float* W2            = (const float*)d_in[9];
    const float* b2            = (const float*)d_in[10];
    const float* g2            = (const float*)d_in[11];
    const float* be2           = (const float*)d_in[12];

    const int Nlast = in_sizes[0] / 3;
    const int Ncur  = in_sizes[2] / 3;
    const int E     = in_sizes[3];
    const int Din   = in_sizes[5] / F_DIM;  // 303

    float *pPC, *pAgg, *pYpre, *pSum1, *pSq1, *pSum2, *pSq2, *pSc1, *pSh1, *pSc2, *pSh2;
    cudaGetSymbolAddress((void**)&pPC,   d_PC);
    cudaGetSymbolAddress((void**)&pAgg,  d_agg);
    cudaGetSymbolAddress((void**)&pYpre, d_ypre);
    cudaGetSymbolAddress((void**)&pSum1, d_colsum1);
    cudaGetSymbolAddress((void**)&pSq1,  d_colsq1);
    cudaGetSymbolAddress((void**)&pSum2, d_colsum2);
    cudaGetSymbolAddress((void**)&pSq2,  d_colsq2);
    cudaGetSymbolAddress((void**)&pSc1,  d_scale1);
    cudaGetSymbolAddress((void**)&pSh1,  d_shift1);
    cudaGetSymbolAddress((void**)&pSc2,  d_scale2);
    cudaGetSymbolAddress((void**)&pSh2,  d_shift2);

    const int NT = (F_DIM + BN - 1) / BN;  // 5 col tiles

    reset_kernel<<<(Ncur + 255) / 256, 256>>>(Ncur);

    gemm_kernel<<<dim3(NT, (Nlast + BM - 1) / BM), 128>>>(
        last_features, last_coors, Nlast, Din, W1, b1, pPC, 0, nullptr, nullptr);

    c2_kernel<<<(Ncur * F_DIM + 255) / 256, 256>>>(current_coors, W1, Ncur);

    count_kernel<<<(E + 255) / 256, 256>>>(cur_idx, E);
    scan_kernel<<<1, 1024>>>(Ncur);
    scatter_kernel<<<(E + 255) / 256, 256>>>(cur_idx, last_idx, E);

    seg_kernel<<<(Ncur + SEGS_PER_BLOCK - 1) / SEGS_PER_BLOCK, 128>>>(Ncur);

    bnparam_kernel<<<(F_DIM + 127) / 128, 128>>>(pSum1, pSq1, 1.0f / (float)E, g1, be1, pSc1, pSh1);
    apply_agg_kernel<<<(Ncur * F_DIM + 255) / 256, 256>>>(Ncur);

    gemm_kernel<<<dim3(NT, (Ncur + BM - 1) / BM), 128>>>(
        pAgg, nullptr, Ncur, F_DIM, W2, b2, pYpre, 1, pSum2, pSq2);

    bnparam_kernel<<<(F_DIM + 127) / 128, 128>>>(pSum2, pSq2, 1.0f / (float)Ncur, g2, be2, pSc2, pSh2);
    apply_out_kernel<<<(Ncur * F_DIM + 255) / 256, 256>>>((float*)d_out, Ncur);
}

// round 4
// speedup vs baseline: 3.8080x; 2.3622x over previous
#include <cuda_runtime.h>
#include <cuda_bf16.h>
#include <cstdint>

#define F_DIM 300
#define KPAD 320           // K padded: 5 chunks of 64
#define NPAD 384           // N padded: 3 tiles of 128
#define MAX_NLAST 100000
#define MAX_NCUR  50000
#define MAX_E     500000

// ---------------- scratch (static __device__; no allocation) ----------------
__device__ float d_PC[(size_t)MAX_NLAST * F_DIM];
__device__ float d_c2[(size_t)MAX_NCUR * F_DIM];
__device__ float d_aggmax[(size_t)MAX_NCUR * F_DIM];
__device__ float d_aggmin[(size_t)MAX_NCUR * F_DIM];
__device__ float d_ypre[(size_t)MAX_NCUR * F_DIM];
__device__ __nv_bfloat16 d_A1hi[(size_t)MAX_NLAST * KPAD];
__device__ __nv_bfloat16 d_A1lo[(size_t)MAX_NLAST * KPAD];
__device__ __nv_bfloat16 d_A2hi[(size_t)MAX_NCUR * KPAD];
__device__ __nv_bfloat16 d_A2lo[(size_t)MAX_NCUR * KPAD];
__device__ __nv_bfloat16 d_W1hi[(size_t)NPAD * KPAD];
__device__ __nv_bfloat16 d_W1lo[(size_t)NPAD * KPAD];
__device__ __nv_bfloat16 d_W2hi[(size_t)NPAD * KPAD];
__device__ __nv_bfloat16 d_W2lo[(size_t)NPAD * KPAD];
__device__ int   d_counts[MAX_NCUR];
__device__ int   d_offsets[MAX_NCUR];
__device__ int   d_cursor[MAX_NCUR];
__device__ int   d_edge_l[MAX_E];
__device__ float d_colsum1[F_DIM], d_colsq1[F_DIM];
__device__ float d_colsum2[F_DIM], d_colsq2[F_DIM];
__device__ float d_scale1[F_DIM], d_shift1[F_DIM];
__device__ float d_scale2[F_DIM], d_shift2[F_DIM];

// ---------------- PTX helpers (all baseline sm_80+, no 'a' features) ----------------
static __device__ __forceinline__ uint32_t smem_u32(const void* p) {
    uint32_t a;
    asm("{ .reg .u64 t; cvta.to.shared.u64 t, %1; cvt.u32.u64 %0, t; }" : "=r"(a) : "l"(p));
    return a;
}
static __device__ __forceinline__ void cp16(uint32_t dst, const void* src, bool pred) {
    int sz = pred ? 16 : 0;
    asm volatile("cp.async.cg.shared.global [%0], [%1], 16, %2;" :: "r"(dst), "l"(src), "r"(sz));
}
#define CP_COMMIT() asm volatile("cp.async.commit_group;" ::: "memory")
#define CP_WAIT(n)  asm volatile("cp.async.wait_group %0;" :: "n"(n) : "memory")

static __device__ __forceinline__ void ldsm_x4(uint32_t* r, uint32_t addr) {
    asm volatile("ldmatrix.sync.aligned.m8n8.x4.shared.b16 {%0,%1,%2,%3}, [%4];"
        : "=r"(r[0]), "=r"(r[1]), "=r"(r[2]), "=r"(r[3]) : "r"(addr));
}
static __device__ __forceinline__ void mma_bf16(float* d, const uint32_t* a, const uint32_t* b) {
    asm volatile("mma.sync.aligned.m16n8k16.row.col.f32.bf16.bf16.f32 "
        "{%0,%1,%2,%3}, {%4,%5,%6,%7}, {%8,%9}, {%0,%1,%2,%3};"
        : "+f"(d[0]), "+f"(d[1]), "+f"(d[2]), "+f"(d[3])
        : "r"(a[0]), "r"(a[1]), "r"(a[2]), "r"(a[3]), "r"(b[0]), "r"(b[1]));
}

// ---------------- tensor-core GEMM: C[M,300] = A[M,KPAD] @ Wt[NPAD,KPAD]^T + bias ----------------
// bf16-split 3 products: Ahi*Bhi + Ahi*Blo + Alo*Bhi. 15 k-chunks of 64.
#define BM 128
#define BN 128
#define BK 64
#define STAGE_A (BM * BK * 2)             // 16384
#define STAGE_B (BN * BK * 2)             // 16384
#define STAGE_BYTES (STAGE_A + STAGE_B)   // 32768
#define GEMM_SMEM (2 * STAGE_BYTES)       // 65536
#define NCHUNK_TOT 15

__global__ __launch_bounds__(128, 1)
void mma_gemm(const __nv_bfloat16* __restrict__ Ahi, const __nv_bfloat16* __restrict__ Alo,
              const __nv_bfloat16* __restrict__ Bhi, const __nv_bfloat16* __restrict__ Blo,
              int M, const float* __restrict__ bias, float* __restrict__ C, int doRelu)
{
    extern __shared__ __align__(128) char smem[];
    const uint32_t sb = smem_u32(smem);
    const int tid = threadIdx.x, wid = tid >> 5, lane = tid & 31;
    const int wm = wid & 1, wn = wid >> 1;          // 2x2 warps, 64x64 tiles
    const int m0 = blockIdx.y * BM;
    const int nb = blockIdx.x;                      // 0..2

    // chunk loader: cc in [0,15): prod = cc/5, kc = cc%5
    auto load_chunk = [&](int cc, int stage) {
        const int prod = cc / 5;
        const int k0 = (cc - prod * 5) * BK;
        const __nv_bfloat16* Asel = (prod == 2) ? Alo : Ahi;
        const __nv_bfloat16* Bsel = (prod == 1) ? Blo : Bhi;
        const uint32_t abase = sb + stage * STAGE_BYTES;
        const uint32_t bbase = abase + STAGE_A;
#pragma unroll
        for (int i = 0; i < 8; i++) {                   // A: 128 rows x 8 chunks
            int lin = i * 128 + tid;
            int row = lin >> 3, ch = lin & 7;
            bool ok = (m0 + row) < M;
            size_t gr = ok ? (size_t)(m0 + row) : 0;
            cp16(abase + row * 128 + ((ch ^ (row & 7)) * 16),
                 Asel + gr * KPAD + k0 + ch * 8, ok);
        }
#pragma unroll
        for (int i = 0; i < 8; i++) {                   // B: 128 rows x 8 chunks
            int lin = i * 128 + tid;
            int row = lin >> 3, ch = lin & 7;
            cp16(bbase + row * 128 + ((ch ^ (row & 7)) * 16),
                 Bsel + (size_t)(nb * 128 + row) * KPAD + k0 + ch * 8, true);
        }
        CP_COMMIT();
    };

    float acc[4][8][4];
#pragma unroll
    for (int mt = 0; mt < 4; mt++)
#pragma unroll
        for (int nt = 0; nt < 8; nt++)
#pragma unroll
            for (int q = 0; q < 4; q++) acc[mt][nt][q] = 0.f;

    load_chunk(0, 0);
    load_chunk(1, 1);

    for (int cc = 0; cc < NCHUNK_TOT; cc++) {
        if (cc < NCHUNK_TOT - 1) { CP_WAIT(1); } else { CP_WAIT(0); }
        __syncthreads();
        const uint32_t abase = sb + (cc & 1) * STAGE_BYTES;
        const uint32_t bbase = abase + STAGE_A;
#pragma unroll
        for (int kk = 0; kk < 4; kk++) {
            uint32_t af[4][4], bf[8][2];
#pragma unroll
            for (int mt = 0; mt < 4; mt++) {
                int row = wm * 64 + mt * 16 + (lane & 15);
                int ch = kk * 2 + (lane >> 4);
                ldsm_x4(af[mt], abase + row * 128 + ((ch ^ (row & 7)) * 16));
            }
#pragma unroll
            for (int np = 0; np < 4; np++) {            // pairs of n8 tiles via x4
                int row = wn * 64 + np * 16 + ((lane >> 4) << 3) + (lane & 7);
                int ch = kk * 2 + ((lane >> 3) & 1);
                uint32_t r4[4];
                ldsm_x4(r4, bbase + row * 128 + ((ch ^ (row & 7)) * 16));
                bf[np * 2][0] = r4[0]; bf[np * 2][1] = r4[1];
                bf[np * 2 + 1][0] = r4[2]; bf[np * 2 + 1][1] = r4[3];
            }
#pragma unroll
            for (int mt = 0; mt < 4; mt++)
#pragma unroll
                for (int nt = 0; nt < 8; nt++)
                    mma_bf16(acc[mt][nt], af[mt], bf[nt]);
        }
        __syncthreads();
        if (cc + 2 < NCHUNK_TOT) load_chunk(cc + 2, cc & 1);
    }

    // epilogue: bias (+relu), masked store
    const int g = lane >> 2, t4 = lane & 3;
    const int c0 = nb * 128 + wn * 64;
#pragma unroll
    for (int mt = 0; mt < 4; mt++) {
#pragma unroll
        for (int half = 0; half < 2; half++) {
            const int row = m0 + wm * 64 + mt * 16 + g + half * 8;
            if (row < M) {
                float* crow = C + (size_t)row * F_DIM;
#pragma unroll
                for (int nt = 0; nt < 8; nt++) {
                    const int col = c0 + nt * 8 + 2 * t4;
                    if (col + 1 < F_DIM) {
                        const float2 bv = *(const float2*)(bias + col);
                        float v0 = acc[mt][nt][half * 2]     + bv.x;
                        float v1 = acc[mt][nt][half * 2 + 1] + bv.y;
                        if (doRelu) { v0 = fmaxf(v0, 0.f); v1 = fmaxf(v1, 0.f); }
                        *(float2*)(crow + col) = make_float2(v0, v1);
                    }
                }
            }
        }
    }
}

// ---------------- conversion kernels ----------------
static __device__ __forceinline__ uint32_t split_pack_hi(float v0, float v1,
                                                         __nv_bfloat16& h0, __nv_bfloat16& h1) {
    h0 = __float2bfloat16(v0); h1 = __float2bfloat16(v1);
    __nv_bfloat162 h = __halves2bfloat162(h0, h1);
    return *(uint32_t*)&h;
}
static __device__ __forceinline__ uint32_t pack_lo(float v0, float v1, __nv_bfloat16 h0, __nv_bfloat16 h1) {
    __nv_bfloat162 l = __floats2bfloat162_rn(v0 - __bfloat162float(h0), v1 - __bfloat162float(h1));
    return *(uint32_t*)&l;
}

__global__ void convA1_kernel(const float* __restrict__ feat, const float* __restrict__ coor, int M) {
    int idx = blockIdx.x * blockDim.x + threadIdx.x;
    if (idx >= M * (KPAD / 2)) return;
    int m = idx / (KPAD / 2), k = (idx % (KPAD / 2)) * 2;
    float v0 = 0.f, v1 = 0.f;
    if (k < F_DIM) v0 = feat[(size_t)m * F_DIM + k];
    else if (k < 303) v0 = coor[(size_t)m * 3 + (k - F_DIM)];
    int k1 = k + 1;
    if (k1 < F_DIM) v1 = feat[(size_t)m * F_DIM + k1];
    else if (k1 < 303) v1 = coor[(size_t)m * 3 + (k1 - F_DIM)];
    __nv_bfloat16 h0, h1;
    uint32_t hp = split_pack_hi(v0, v1, h0, h1);
    uint32_t lp = pack_lo(v0, v1, h0, h1);
    *(uint32_t*)(d_A1hi + (size_t)m * KPAD + k) = hp;
    *(uint32_t*)(d_A1lo + (size_t)m * KPAD + k) = lp;
}

__global__ void convW_kernel(const float* __restrict__ W, int Krows,
                             __nv_bfloat16* __restrict__ hi, __nv_bfloat16* __restrict__ lo) {
    int idx = blockIdx.x * blockDim.x + threadIdx.x;
    if (idx >= NPAD * (KPAD / 2)) return;
    int n = idx / (KPAD / 2), k = (idx % (KPAD / 2)) * 2;
    float v0 = (n < F_DIM && k < Krows) ? W[(size_t)k * F_DIM + n] : 0.f;
    float v1 = (n < F_DIM && k + 1 < Krows) ? W[(size_t)(k + 1) * F_DIM + n] : 0.f;
    __nv_bfloat16 h0, h1;
    uint32_t hp = split_pack_hi(v0, v1, h0, h1);
    uint32_t lp = pack_lo(v0, v1, h0, h1);
    *(uint32_t*)(hi + (size_t)n * KPAD + k) = hp;
    *(uint32_t*)(lo + (size_t)n * KPAD + k) = lp;
}

// BN1 apply on segment max/min, write bf16 split A2 directly
__global__ void apply_agg_conv_kernel(int ncur) {
    int idx = blockIdx.x * blockDim.x + threadIdx.x;
    if (idx >= ncur * (KPAD / 2)) return;
    int rw = idx / (KPAD / 2), k = (idx % (KPAD / 2)) * 2;
    float v0 = 0.f, v1 = 0.f;
    if (k < F_DIM) {
        float m = d_aggmax[(size_t)rw * F_DIM + k];
        if (m >= 0.f) {
            float sc = d_scale1[k];
            float b = (sc >= 0.f) ? m : d_aggmin[(size_t)rw * F_DIM + k];
            v0 = fmaf(b, sc, d_shift1[k]);
        }
    }
    if (k + 1 < F_DIM) {
        float m = d_aggmax[(size_t)rw * F_DIM + k + 1];
        if (m >= 0.f) {
            float sc = d_scale1[k + 1];
            float b = (sc >= 0.f) ? m : d_aggmin[(size_t)rw * F_DIM + k + 1];
            v1 = fmaf(b, sc, d_shift1[k + 1]);
        }
    }
    __nv_bfloat16 h0, h1;
    uint32_t hp = split_pack_hi(v0, v1, h0, h1);
    uint32_t lp = pack_lo(v0, v1, h0, h1);
    *(uint32_t*)(d_A2hi + (size_t)rw * KPAD + k) = hp;
    *(uint32_t*)(d_A2lo + (size_t)rw * KPAD + k) = lp;
}

// ---------------- graph/CSR + misc kernels ----------------
__global__ void reset_kernel(int ncur) {
    int i = blockIdx.x * blockDim.x + threadIdx.x;
    if (i < ncur) d_counts[i] = 0;
    if (i < F_DIM) {
        d_colsum1[i] = 0.f; d_colsq1[i] = 0.f;
        d_colsum2[i] = 0.f; d_colsq2[i] = 0.f;
    }
}

__global__ void c2_kernel(const float* __restrict__ ccoors, const float* __restrict__ W1, int ncur) {
    int idx = blockIdx.x * blockDim.x + threadIdx.x;
    if (idx >= ncur * F_DIM) return;
    int i = idx / F_DIM, c = idx % F_DIM;
    float x = ccoors[3 * i], y = ccoors[3 * i + 1], z = ccoors[3 * i + 2];
    d_c2[idx] = x * W1[(size_t)300 * F_DIM + c]
              + y * W1[(size_t)301 * F_DIM + c]
              + z * W1[(size_t)302 * F_DIM + c];
}

__global__ void count_kernel(const int* __restrict__ cur_idx, int E) {
    int e = blockIdx.x * blockDim.x + threadIdx.x;
    if (e < E) atomicAdd(&d_counts[cur_idx[e]], 1);
}

__global__ void scan_kernel(int n) {
    __shared__ int buf[1024];
    __shared__ int carry_s;
    int tid = threadIdx.x;
    if (tid == 0) carry_s = 0;
    __syncthreads();
    for (int base = 0; base < n; base += 1024) {
        int i = base + tid;
        int x = (i < n) ? d_counts[i] : 0;
        buf[tid] = x;
        __syncthreads();
        for (int off = 1; off < 1024; off <<= 1) {
            int v = (tid >= off) ? buf[tid - off] : 0;
            __syncthreads();
            buf[tid] += v;
            __syncthreads();
        }
        int carry = carry_s;
        int excl = carry + buf[tid] - x;
        if (i < n) { d_offsets[i] = excl; d_cursor[i] = excl; }
        __syncthreads();
        if (tid == 1023) carry_s = carry + buf[1023];
        __syncthreads();
    }
}

__global__ void scatter_kernel(const int* __restrict__ cur_idx, const int* __restrict__ last_idx, int E) {
    int e = blockIdx.x * blockDim.x + threadIdx.x;
    if (e < E) {
        int p = atomicAdd(&d_cursor[cur_idx[e]], 1);
        d_edge_l[p] = last_idx[e];
    }
}

#define SEGS_PER_BLOCK 4
__global__ __launch_bounds__(128) void seg_kernel(int ncur) {
    const int tid = threadIdx.x;
    const int ca = tid, cb = tid + 128, cc = tid + 256;
    const bool h2 = (cc < F_DIM);
    float s0 = 0.f, s1 = 0.f, s2 = 0.f, q0 = 0.f, q1 = 0.f, q2 = 0.f;

    int segBeg = blockIdx.x * SEGS_PER_BLOCK;
    int segEnd = min(segBeg + SEGS_PER_BLOCK, ncur);
    for (int seg = segBeg; seg < segEnd; seg++) {
        const float* c2r = d_c2 + (size_t)seg * F_DIM;
        float cA = c2r[ca], cB = c2r[cb], cC = h2 ? c2r[cc] : 0.f;
        float mxA = -1.f, mxB = -1.f, mxC = -1.f;
        float mnA = 3.4e38f, mnB = 3.4e38f, mnC = 3.4e38f;
        int off = d_offsets[seg], cnt = d_counts[seg];
        int t = 0;
        for (; t + 4 <= cnt; t += 4) {
            int l[4];
#pragma unroll
            for (int u = 0; u < 4; u++) l[u] = d_edge_l[off + t + u];
            float vA[4], vB[4], vC[4];
#pragma unroll
            for (int u = 0; u < 4; u++) {
                const float* p = d_PC + (size_t)l[u] * F_DIM;
                vA[u] = p[ca]; vB[u] = p[cb]; vC[u] = h2 ? p[cc] : 0.f;
            }
#pragma unroll
            for (int u = 0; u < 4; u++) {
                float a = fmaxf(vA[u] - cA, 0.f);
                float b = fmaxf(vB[u] - cB, 0.f);
                float c = fmaxf(vC[u] - cC, 0.f);
                s0 += a; q0 += a * a; mxA = fmaxf(mxA, a); mnA = fminf(mnA, a);
                s1 += b; q1 += b * b; mxB = fmaxf(mxB, b); mnB = fminf(mnB, b);
                s2 += c; q2 += c * c; mxC = fmaxf(mxC, c); mnC = fminf(mnC, c);
            }
        }
        for (; t < cnt; t++) {
            int lv = d_edge_l[off + t];
            const float* p = d_PC + (size_t)lv * F_DIM;
            float a = fmaxf(p[ca] - cA, 0.f);
            float b = fmaxf(p[cb] - cB, 0.f);
            float c = h2 ? fmaxf(p[cc] - cC, 0.f) : 0.f;
            s0 += a; q0 += a * a; mxA = fmaxf(mxA, a); mnA = fminf(mnA, a);
            s1 += b; q1 += b * b; mxB = fmaxf(mxB, b); mnB = fminf(mnB, b);
            s2 += c; q2 += c * c; mxC = fmaxf(mxC, c); mnC = fminf(mnC, c);
        }
        size_t base = (size_t)seg * F_DIM;
        d_aggmax[base + ca] = mxA; d_aggmin[base + ca] = cnt ? mnA : 0.f;
        d_aggmax[base + cb] = mxB; d_aggmin[base + cb] = cnt ? mnB : 0.f;
        if (h2) { d_aggmax[base + cc] = mxC; d_aggmin[base + cc] = cnt ? mnC : 0.f; }
    }
    atomicAdd(&d_colsum1[ca], s0); atomicAdd(&d_colsq1[ca], q0);
    atomicAdd(&d_colsum1[cb], s1); atomicAdd(&d_colsq1[cb], q1);
    if (h2) { atomicAdd(&d_colsum1[cc], s2); atomicAdd(&d_colsq1[cc], q2); }
}

__global__ void bnparam_kernel(const float* __restrict__ colsum, const float* __restrict__ colsq,
                               float invN, const float* __restrict__ g, const float* __restrict__ be,
                               float* __restrict__ scale, float* __restrict__ shift) {
    int c = blockIdx.x * blockDim.x + threadIdx.x;
    if (c >= F_DIM) return;
    float mean = colsum[c] * invN;
    float var = colsq[c] * invN - mean * mean;
    if (var < 0.f) var = 0.f;
    float sc = g[c] * rsqrtf(var + 1e-5f);
    scale[c] = sc;
    shift[c] = be[c] - mean * sc;
}

// column stats over ypre [ncur,300]
__global__ void stats2_kernel(int ncur) {
    int col = threadIdx.x;
    if (col >= F_DIM) return;
    float s = 0.f, q = 0.f;
    for (int r = blockIdx.x; r < ncur; r += gridDim.x) {
        float v = d_ypre[(size_t)r * F_DIM + col];
        s += v; q += v * v;
    }
    atomicAdd(&d_colsum2[col], s);
    atomicAdd(&d_colsq2[col], q);
}

__global__ void apply_out_kernel(float* __restrict__ out, int ncur) {
    int idx = blockIdx.x * blockDim.x + threadIdx.x;
    if (idx >= ncur * F_DIM) return;
    int c = idx % F_DIM;
    out[idx] = fmaf(d_ypre[idx], d_scale2[c], d_shift2[c]);
}

// ---------------- launcher ----------------
extern "C" void kernel_launch(void* const* d_in, const int* in_sizes, int n_in,
                              void* d_out, int out_size) {
    const float* last_coors    = (const float*)d_in[0];
    const float* last_features = (const float*)d_in[1];
    const float* current_coors = (const float*)d_in[2];
    const int*   cur_idx       = (const int*)d_in[3];
    const int*   last_idx      = (const int*)d_in[4];
    const float* W1            = (const float*)d_in[5];
    const float* b1            = (const float*)d_in[6];
    const float* g1            = (const float*)d_in[7];
    const float* be1           = (const float*)d_in[8];
    const float* W2            = (const float*)d_in[9];
    const float* b2            = (const float*)d_in[10];
    const float* g2            = (const float*)d_in[11];
    const float* be2           = (const float*)d_in[12];

    const int Nlast = in_sizes[0] / 3;
    const int Ncur  = in_sizes[2] / 3;
    const int E     = in_sizes[3];

    float *pPC, *pYpre, *pSum1, *pSq1, *pSum2, *pSq2, *pSc1, *pSh1, *pSc2, *pSh2;
    __nv_bfloat16 *pA1h, *pA1l, *pA2h, *pA2l, *pW1h, *pW1l, *pW2h, *pW2l;
    cudaGetSymbolAddress((void**)&pPC,   d_PC);
    cudaGetSymbolAddress((void**)&pYpre, d_ypre);
    cudaGetSymbolAddress((void**)&pSum1, d_colsum1);
    cudaGetSymbolAddress((void**)&pSq1,  d_colsq1);
    cudaGetSymbolAddress((void**)&pSum2, d_colsum2);
    cudaGetSymbolAddress((void**)&pSq2,  d_colsq2);
    cudaGetSymbolAddress((void**)&pSc1,  d_scale1);
    cudaGetSymbolAddress((void**)&pSh1,  d_shift1);
    cudaGetSymbolAddress((void**)&pSc2,  d_scale2);
    cudaGetSymbolAddress((void**)&pSh2,  d_shift2);
    cudaGetSymbolAddress((void**)&pA1h,  d_A1hi);
    cudaGetSymbolAddress((void**)&pA1l,  d_A1lo);
    cudaGetSymbolAddress((void**)&pA2h,  d_A2hi);
    cudaGetSymbolAddress((void**)&pA2l,  d_A2lo);
    cudaGetSymbolAddress((void**)&pW1h,  d_W1hi);
    cudaGetSymbolAddress((void**)&pW1l,  d_W1lo);
    cudaGetSymbolAddress((void**)&pW2h,  d_W2hi);
    cudaGetSymbolAddress((void**)&pW2l,  d_W2lo);

    cudaFuncSetAttribute(mma_gemm, cudaFuncAttributeMaxDynamicSharedMemorySize, GEMM_SMEM);

    reset_kernel<<<(Ncur + 255) / 256, 256>>>(Ncur);
    convW_kernel<<<(NPAD * (KPAD / 2) + 255) / 256, 256>>>(W1, 303, pW1h, pW1l);
    convW_kernel<<<(NPAD * (KPAD / 2) + 255) / 256, 256>>>(W2, 300, pW2h, pW2l);
    convA1_kernel<<<(Nlast * (KPAD / 2) + 255) / 256, 256>>>(last_features, last_coors, Nlast);
    c2_kernel<<<(Ncur * F_DIM + 255) / 256, 256>>>(current_coors, W1, Ncur);
    count_kernel<<<(E + 255) / 256, 256>>>(cur_idx, E);
    scan_kernel<<<1, 1024>>>(Ncur);
    scatter_kernel<<<(E + 255) / 256, 256>>>(cur_idx, last_idx, E);

    // GEMM1: PC = [feat|coor] @ W1 + b1
    mma_gemm<<<dim3(3, (Nlast + BM - 1) / BM), 128, GEMM_SMEM>>>(
        pA1h, pA1l, pW1h, pW1l, Nlast, b1, pPC, 0);

    seg_kernel<<<(Ncur + SEGS_PER_BLOCK - 1) / SEGS_PER_BLOCK, 128>>>(Ncur);
    bnparam_kernel<<<(F_DIM + 127) / 128, 128>>>(pSum1, pSq1, 1.0f / (float)E, g1, be1, pSc1, pSh1);
    apply_agg_conv_kernel<<<(Ncur * (KPAD / 2) + 255) / 256, 256>>>(Ncur);

    // GEMM2: ypre = relu(agg @ W2 + b2)
    mma_gemm<<<dim3(3, (Ncur + BM - 1) / BM), 128, GEMM_SMEM>>>(
        pA2h, pA2l, pW2h, pW2l, Ncur, b2, pYpre, 1);

    stats2_kernel<<<256, 320>>>(Ncur);
    bnparam_kernel<<<(F_DIM + 127) / 128, 128>>>(pSum2, pSq2, 1.0f / (float)Ncur, g2, be2, pSc2, pSh2);
    apply_out_kernel<<<(Ncur * F_DIM + 255) / 256, 256>>>((float*)d_out, Ncur);
}